// round 13
// baseline (speedup 1.0000x reference)
#include <cuda_runtime.h>
#include <cuda_fp16.h>
#include <cstdint>

constexpr int TPB  = 128;   // 4 warps, each owns M=32 rows
constexpr int TILE = 128;

// ---- weight SMEM: per-region row strides ≡ 16·odd (mod 128) -> ldmatrix
// conflict-free, linear addressing (SASS immediate offsets).
constexpr int ST_S0 = 48;    // K=16 (32B data)
constexpr int ST_C0 = 80;    // K=32 (64B data)
constexpr int ST_64 = 144;   // K=64 (128B data)

constexpr int RB_S0 = 0;                        // 64 rows x 48
constexpr int RB_S1 = RB_S0 + 64*ST_S0;         // 64 x 144
constexpr int RB_S2 = RB_S1 + 64*ST_64;         // 16 x 144
constexpr int RB_C0 = RB_S2 + 16*ST_64;         // 64 x 80
constexpr int RB_C1 = RB_C0 + 64*ST_C0;         // 64 x 144
constexpr int RB_C2 = RB_C1 + 64*ST_64;         // 64 x 144
constexpr int RB_C3 = RB_C2 + 64*ST_64;         // 8 x 144
constexpr int WT_BYTES = RB_C3 + 8*ST_64;       // 39296

constexpr int SM_OUT = WT_BYTES;                // 4w * 32r * 5 f32 (stride 5: bank-clean)
constexpr int SMEM_TOTAL = SM_OUT + 4*32*5*4;   // 41856

// ---------------- PTX helpers ----------------
__device__ __forceinline__ uint32_t smem_u32(const void* p) {
    uint32_t a; asm("{ .reg .u64 t; cvta.to.shared.u64 t, %1; cvt.u32.u64 %0, t; }" : "=r"(a) : "l"(p));
    return a;
}
// fp32-accumulator MMA (used for S2 and C3 only)
__device__ __forceinline__ void mma16816(float c[4], const uint32_t a[4], uint32_t b0, uint32_t b1) {
    asm volatile("mma.sync.aligned.m16n8k16.row.col.f32.f16.f16.f32 "
        "{%0,%1,%2,%3},{%4,%5,%6,%7},{%8,%9},{%0,%1,%2,%3};"
        : "+f"(c[0]), "+f"(c[1]), "+f"(c[2]), "+f"(c[3])
        : "r"(a[0]), "r"(a[1]), "r"(a[2]), "r"(a[3]), "r"(b0), "r"(b1));
}
// fp16-accumulator MMA (hidden layers): D frag = 2 x f16x2, ALREADY in A-frag word layout
__device__ __forceinline__ void mma16816h(uint32_t d[2], const uint32_t a[4], uint32_t b0, uint32_t b1) {
    asm volatile("mma.sync.aligned.m16n8k16.row.col.f16.f16.f16.f16 "
        "{%0,%1},{%2,%3,%4,%5},{%6,%7},{%0,%1};"
        : "+r"(d[0]), "+r"(d[1])
        : "r"(a[0]), "r"(a[1]), "r"(a[2]), "r"(a[3]), "r"(b0), "r"(b1));
}
__device__ __forceinline__ void ldm4(uint32_t r[4], uint32_t addr) {
    asm volatile("ldmatrix.sync.aligned.m8n8.x4.shared.b16 {%0,%1,%2,%3}, [%4];"
        : "=r"(r[0]), "=r"(r[1]), "=r"(r[2]), "=r"(r[3]) : "r"(addr));
}
__device__ __forceinline__ void ldm2(uint32_t r[2], uint32_t addr) {
    asm volatile("ldmatrix.sync.aligned.m8n8.x2.shared.b16 {%0,%1}, [%2];"
        : "=r"(r[0]), "=r"(r[1]) : "r"(addr));
}
__device__ __forceinline__ uint32_t pack2(float f0, float f1) {
    uint32_t h;
    asm("cvt.rn.f16x2.f32 %0, %1, %2;" : "=r"(h) : "f"(f1), "f"(f0));
    return h;
}
__device__ __forceinline__ uint32_t relu2(uint32_t v) {
    uint32_t r;
    asm("max.f16x2 %0, %1, %2;" : "=r"(r) : "r"(v), "r"(0u));
    return r;
}
__device__ __forceinline__ uint32_t shfl_u(uint32_t v, int src) {
    return __shfl_sync(0xffffffffu, v, src);
}

// ---- hidden layer, fp16 acc, KT-MAJOR flat stream ----
template<int KT, int STRIDE, int RBASE>
__device__ __forceinline__ void layer_h(uint32_t abase,
                                        const uint32_t ain[2][4][4],
                                        uint32_t aout[2][4][4])
{
    uint32_t D[4][2][2][2];
    #pragma unroll
    for (int np = 0; np < 4; np++)
        #pragma unroll
        for (int b = 0; b < 2; b++)
            #pragma unroll
            for (int nt = 0; nt < 2; nt++) { D[np][b][nt][0] = 0u; D[np][b][nt][1] = 0u; }

    uint32_t bh[2][4];
    ldm4(bh[0], abase + (uint32_t)RBASE);

    #pragma unroll
    for (int idx = 0; idx < KT * 4; idx++) {
        const int kt = idx >> 2, np = idx & 3;          // kt-major, np inner
        if (idx + 1 < KT * 4) {
            const int kt1 = (idx + 1) >> 2, np1 = (idx + 1) & 3;
            ldm4(bh[(idx + 1) & 1],
                 abase + (uint32_t)(RBASE + np1 * 16 * STRIDE + kt1 * 32));
        }
        const uint32_t* cur = bh[idx & 1];
        #pragma unroll
        for (int b = 0; b < 2; b++) {
            mma16816h(D[np][b][0], ain[b][kt], cur[0], cur[1]);
            mma16816h(D[np][b][1], ain[b][kt], cur[2], cur[3]);
        }
    }
    #pragma unroll
    for (int np = 0; np < 4; np++)
        #pragma unroll
        for (int b = 0; b < 2; b++) {
            aout[b][np][0] = relu2(D[np][b][0][0]);
            aout[b][np][1] = relu2(D[np][b][0][1]);
            aout[b][np][2] = relu2(D[np][b][1][0]);
            aout[b][np][3] = relu2(D[np][b][1][1]);
        }
}

// store W[K][N] (row-major) transposed into padded rows, fp16
__device__ __forceinline__ void fill_w(const float* __restrict__ W, int K, int N,
                                       int rbase, int stride, char* smem, int tid)
{
    char* wdst = smem + rbase;
    for (int idx = tid; idx < K * N; idx += TPB) {
        int k = idx / N, nn = idx % N;
        __half hb = __float2half(W[idx]);
        *reinterpret_cast<uint16_t*>(wdst + nn * stride + 2 * k) =
            *reinterpret_cast<uint16_t*>(&hb);
    }
}
// wc0 with permuted K rows: src 0..2 (views) -> k 16..18; src 3..17 (g1..g15) -> k 1..15.
__device__ __forceinline__ void fill_wc0(const float* __restrict__ W, char* smem, int tid)
{
    char* wdst = smem + RB_C0;
    for (int idx = tid; idx < 18 * 64; idx += TPB) {
        int k = idx / 64, nn = idx % 64;
        int kd = (k < 3) ? (16 + k) : (k - 2);
        __half hb = __float2half(W[idx]);
        *reinterpret_cast<uint16_t*>(wdst + nn * ST_C0 + 2 * kd) =
            *reinterpret_cast<uint16_t*>(&hb);
    }
}

__global__ void __launch_bounds__(TPB, 4) nerf_hmma_kernel(
    const float* __restrict__ x,
    const float* __restrict__ ws0, const float* __restrict__ ws1,
    const float* __restrict__ ws2, const float* __restrict__ wc0,
    const float* __restrict__ wc1, const float* __restrict__ wc2,
    const float* __restrict__ wc3,
    float* __restrict__ out, int n)
{
    extern __shared__ char sm[];
    const uint32_t smb = smem_u32(sm);
    const int tid  = threadIdx.x;
    const int wid  = tid >> 5;
    const int lane = tid & 31;
    const int g4   = lane >> 2;
    const int m4   = lane & 3;

    for (int t = tid; t < WT_BYTES / 4; t += TPB)
        reinterpret_cast<uint32_t*>(sm)[t] = 0u;
    __syncthreads();
    fill_w(ws0,  3, 64, RB_S0, ST_S0, sm, tid);
    fill_w(ws1, 64, 64, RB_S1, ST_64, sm, tid);
    fill_w(ws2, 64, 16, RB_S2, ST_64, sm, tid);
    fill_wc0(wc0, sm, tid);
    fill_w(wc1, 64, 64, RB_C1, ST_64, sm, tid);
    fill_w(wc2, 64, 64, RB_C2, ST_64, sm, tid);
    fill_w(wc3, 64,  3, RB_C3, ST_64, sm, tid);
    __syncthreads();

    // ---- convoy breaker: same-SM CTA cohorts (bid, bid+148, +296, +444) get a
    // one-time serial-FFMA phase skew of ~phase/4 of one tile's wall time.
    // Uniform per-tile cost keeps the offset for the whole persistent loop.
    {
        const int phase = (int)(blockIdx.x / 148u) & 3;
        float acc = 1.0f + (float)lane;
        #pragma unroll 1
        for (int i = 0; i < phase * 830; i++)
            asm volatile("fma.rn.f32 %0, %0, 0f3F800001, 0f33800000;" : "+f"(acc));
        // dead-store guard (never taken; acc > 0 always)
        if (acc < 0.0f) reinterpret_cast<float*>(sm)[0] = acc;
    }

    // per-lane ldmatrix base addresses (one per stride class)
    const int mm = lane >> 3, rr = lane & 7;
    const int qrow = ((mm >= 2) ? 8 : 0) + rr;
    const uint32_t tsel = (mm & 1) ? 16u : 0u;
    const uint32_t a48  = smb + (uint32_t)(qrow * ST_S0) + tsel;
    const uint32_t a80  = smb + (uint32_t)(qrow * ST_C0) + tsel;
    const uint32_t a144 = smb + (uint32_t)(qrow * ST_64) + tsel;
    const uint32_t a2   = smb + (uint32_t)(rr   * ST_64) + tsel;   // ldm2 (C3)

    float* outb = reinterpret_cast<float*>(sm + SM_OUT) + wid * 32 * 5;   // [32][5]

    const int ntiles = n / TILE;

    // ---- prefetch first tile's x into registers ----
    float2 p01, p23, p45;
    int tile = blockIdx.x;
    if (tile < ntiles) {
        const float* xr = x + (size_t)(tile * TILE + wid * 32 + lane) * 6;
        p01 = *reinterpret_cast<const float2*>(xr);
        p23 = *reinterpret_cast<const float2*>(xr + 2);
        p45 = *reinterpret_cast<const float2*>(xr + 4);
    }

    #pragma unroll 1
    for (; tile < ntiles; tile += gridDim.x) {
        const int rowg = tile * TILE + wid * 32;

        const uint32_t w0 = pack2(p01.x, p01.y);   // pts x,y
        const uint32_t w1 = pack2(p23.x, 0.0f);    // pts z
        const uint32_t w8 = pack2(p23.y, p45.x);   // views vx,vy
        const uint32_t w9 = pack2(p45.y, 0.0f);    // view  vz

        const int tnext = tile + gridDim.x;
        if (tnext < ntiles) {
            const float* xr = x + (size_t)(tnext * TILE + wid * 32 + lane) * 6;
            p01 = *reinterpret_cast<const float2*>(xr);
            p23 = *reinterpret_cast<const float2*>(xr + 2);
            p45 = *reinterpret_cast<const float2*>(xr + 4);
        }

        uint32_t A0[2][4][4], A1[2][4][4];

        // ---- build S0 A frags via shfl ----
        #pragma unroll
        for (int b = 0; b < 2; b++) {
            int r0 = b*16 + g4, r1 = r0 + 8;
            uint32_t u00 = shfl_u(w0, r0), u01 = shfl_u(w1, r0);
            uint32_t u10 = shfl_u(w0, r1), u11 = shfl_u(w1, r1);
            A0[b][0][0] = (m4 == 0) ? u00 : (m4 == 1) ? u01 : 0u;
            A0[b][0][1] = (m4 == 0) ? u10 : (m4 == 1) ? u11 : 0u;
            A0[b][0][2] = 0u;
            A0[b][0][3] = 0u;
        }

        // ---- S0: 16 -> 64; S1: 64 -> 64 (fp16 acc, kt-major) ----
        layer_h<1, ST_S0, RB_S0>(a48,  A0, A1);
        layer_h<4, ST_64, RB_S1>(a144, A1, A0);

        // ---- S2: 64 -> 16 (fp32 acc, no relu) ----
        float Cs[2][2][4];
        {
            #pragma unroll
            for (int b = 0; b < 2; b++)
                #pragma unroll
                for (int j = 0; j < 2; j++)
                    #pragma unroll
                    for (int i = 0; i < 4; i++) Cs[b][j][i] = 0.0f;
            uint32_t bh[2][4];
            ldm4(bh[0], a144 + (uint32_t)RB_S2);
            #pragma unroll
            for (int kt = 0; kt < 4; kt++) {
                if (kt + 1 < 4)
                    ldm4(bh[(kt + 1) & 1], a144 + (uint32_t)(RB_S2 + (kt + 1) * 32));
                const uint32_t* cur = bh[kt & 1];
                #pragma unroll
                for (int b = 0; b < 2; b++) {
                    mma16816(Cs[b][0], A0[b][kt], cur[0], cur[1]);
                    mma16816(Cs[b][1], A0[b][kt], cur[2], cur[3]);
                }
            }
        }

        // sigma: lane m4==0 holds col 0 (g0) for rows r0 and r1
        #pragma unroll
        for (int b = 0; b < 2; b++) {
            if (m4 == 0) {
                int r0 = b*16 + g4, r1 = r0 + 8;
                float v0 = Cs[b][0][0], v2 = Cs[b][0][2];
                outb[r0*5 + 3] = fmaxf(v0, 0.f) + log1pf(expf(-fabsf(v0)));
                outb[r1*5 + 3] = fmaxf(v2, 0.f) + log1pf(expf(-fabsf(v2)));
            }
        }

        // ---- build C0 A frags: kt=0 in-lane repack of S2 C-frags; kt=1 views via shfl ----
        #pragma unroll
        for (int b = 0; b < 2; b++) {
            A0[b][0][0] = pack2(Cs[b][0][0], Cs[b][0][1]);
            A0[b][0][1] = pack2(Cs[b][0][2], Cs[b][0][3]);
            A0[b][0][2] = pack2(Cs[b][1][0], Cs[b][1][1]);
            A0[b][0][3] = pack2(Cs[b][1][2], Cs[b][1][3]);
            int r0 = b*16 + g4, r1 = r0 + 8;
            uint32_t v00 = shfl_u(w8, r0), v01 = shfl_u(w9, r0);
            uint32_t v10 = shfl_u(w8, r1), v11 = shfl_u(w9, r1);
            A0[b][1][0] = (m4 == 0) ? v00 : (m4 == 1) ? v01 : 0u;
            A0[b][1][1] = (m4 == 0) ? v10 : (m4 == 1) ? v11 : 0u;
            A0[b][1][2] = 0u;
            A0[b][1][3] = 0u;
        }

        // ---- C0: 32 -> 64; C1, C2: 64 -> 64 (fp16 acc, kt-major) ----
        layer_h<2, ST_C0, RB_C0>(a80,  A0, A1);
        layer_h<4, ST_64, RB_C1>(a144, A1, A0);
        layer_h<4, ST_64, RB_C2>(a144, A0, A1);

        // ---- C3: 64 -> 3 (fp32 acc, N padded to 8), pipelined ldm2 ----
        {
            float Cc[2][4];
            #pragma unroll
            for (int b = 0; b < 2; b++)
                #pragma unroll
                for (int i = 0; i < 4; i++) Cc[b][i] = 0.0f;
            uint32_t bh[2][2];
            ldm2(bh[0], a2 + (uint32_t)RB_C3);
            #pragma unroll
            for (int kt = 0; kt < 4; kt++) {
                if (kt + 1 < 4)
                    ldm2(bh[(kt + 1) & 1], a2 + (uint32_t)(RB_C3 + (kt + 1) * 32));
                const uint32_t* cur = bh[kt & 1];
                #pragma unroll
                for (int b = 0; b < 2; b++) mma16816(Cc[b], A1[b][kt], cur[0], cur[1]);
            }
            #pragma unroll
            for (int b = 0; b < 2; b++) {
                int r0 = b*16 + g4, r1 = r0 + 8;
                if (m4 == 0) {
                    outb[r0*5+0] = Cc[b][0]; outb[r0*5+1] = Cc[b][1];
                    outb[r1*5+0] = Cc[b][2]; outb[r1*5+1] = Cc[b][3];
                } else if (m4 == 1) {
                    outb[r0*5+2] = Cc[b][0];
                    outb[r1*5+2] = Cc[b][2];
                }
            }
        }
        __syncwarp();

        // ---- final store: lane l writes row l ----
        {
            float4 r;
            r.x = outb[lane*5+0]; r.y = outb[lane*5+1];
            r.z = outb[lane*5+2]; r.w = outb[lane*5+3];
            reinterpret_cast<float4*>(out)[rowg + lane] = r;
        }
        __syncwarp();
    }
}

extern "C" void kernel_launch(void* const* d_in, const int* in_sizes, int n_in,
                              void* d_out, int out_size) {
    const float* x   = (const float*)d_in[0];
    const float* ws0 = (const float*)d_in[1];
    const float* ws1 = (const float*)d_in[2];
    const float* ws2 = (const float*)d_in[3];
    const float* wc0 = (const float*)d_in[4];
    const float* wc1 = (const float*)d_in[5];
    const float* wc2 = (const float*)d_in[6];
    const float* wc3 = (const float*)d_in[7];
    float* out = (float*)d_out;

    int n = in_sizes[0] / 6;
    int ntiles = n / TILE;

    cudaFuncSetAttribute(nerf_hmma_kernel,
                         cudaFuncAttributeMaxDynamicSharedMemorySize, SMEM_TOTAL);
    int grid = 592;                      // 4 persistent CTAs per SM
    if (grid > ntiles) grid = ntiles;
    nerf_hmma_kernel<<<grid, TPB, SMEM_TOTAL>>>(x, ws0, ws1, ws2, wc0, wc1, wc2, wc3, out, n);
}

// round 14
// speedup vs baseline: 1.2090x; 1.2090x over previous
#include <cuda_runtime.h>
#include <cuda_fp16.h>
#include <cstdint>

constexpr int TPB  = 128;   // 4 warps, each owns M=32 rows of TWO tiles
constexpr int TILE = 128;

// ---- weight SMEM: per-region row strides ≡ 16·odd (mod 128) -> ldmatrix
// conflict-free, linear addressing (SASS immediate offsets).
constexpr int ST_S0 = 48;    // K=16 (32B data)
constexpr int ST_C0 = 80;    // K=32 (64B data)
constexpr int ST_64 = 144;   // K=64 (128B data)

constexpr int RB_S0 = 0;                        // 64 rows x 48
constexpr int RB_S1 = RB_S0 + 64*ST_S0;         // 64 x 144
constexpr int RB_S2 = RB_S1 + 64*ST_64;         // 16 x 144
constexpr int RB_C0 = RB_S2 + 16*ST_64;         // 64 x 80
constexpr int RB_C1 = RB_C0 + 64*ST_C0;         // 64 x 144
constexpr int RB_C2 = RB_C1 + 64*ST_64;         // 64 x 144
constexpr int RB_C3 = RB_C2 + 64*ST_64;         // 8 x 144
constexpr int WT_BYTES = RB_C3 + 8*ST_64;       // 39296

constexpr int SM_OUT = WT_BYTES;                // 4w * 2tiles * 32r * 5 f32
constexpr int SMEM_TOTAL = SM_OUT + 4*2*32*5*4; // 44416 -> 2 CTAs/SM

// ---------------- PTX helpers ----------------
__device__ __forceinline__ uint32_t smem_u32(const void* p) {
    uint32_t a; asm("{ .reg .u64 t; cvta.to.shared.u64 t, %1; cvt.u32.u64 %0, t; }" : "=r"(a) : "l"(p));
    return a;
}
__device__ __forceinline__ void mma16816(float c[4], const uint32_t a[4], uint32_t b0, uint32_t b1) {
    asm volatile("mma.sync.aligned.m16n8k16.row.col.f32.f16.f16.f32 "
        "{%0,%1,%2,%3},{%4,%5,%6,%7},{%8,%9},{%0,%1,%2,%3};"
        : "+f"(c[0]), "+f"(c[1]), "+f"(c[2]), "+f"(c[3])
        : "r"(a[0]), "r"(a[1]), "r"(a[2]), "r"(a[3]), "r"(b0), "r"(b1));
}
__device__ __forceinline__ void mma16816h(uint32_t d[2], const uint32_t a[4], uint32_t b0, uint32_t b1) {
    asm volatile("mma.sync.aligned.m16n8k16.row.col.f16.f16.f16.f16 "
        "{%0,%1},{%2,%3,%4,%5},{%6,%7},{%0,%1};"
        : "+r"(d[0]), "+r"(d[1])
        : "r"(a[0]), "r"(a[1]), "r"(a[2]), "r"(a[3]), "r"(b0), "r"(b1));
}
__device__ __forceinline__ void ldm4(uint32_t r[4], uint32_t addr) {
    asm volatile("ldmatrix.sync.aligned.m8n8.x4.shared.b16 {%0,%1,%2,%3}, [%4];"
        : "=r"(r[0]), "=r"(r[1]), "=r"(r[2]), "=r"(r[3]) : "r"(addr));
}
__device__ __forceinline__ void ldm2(uint32_t r[2], uint32_t addr) {
    asm volatile("ldmatrix.sync.aligned.m8n8.x2.shared.b16 {%0,%1}, [%2];"
        : "=r"(r[0]), "=r"(r[1]) : "r"(addr));
}
__device__ __forceinline__ uint32_t pack2(float f0, float f1) {
    uint32_t h;
    asm("cvt.rn.f16x2.f32 %0, %1, %2;" : "=r"(h) : "f"(f1), "f"(f0));
    return h;
}
__device__ __forceinline__ uint32_t relu2(uint32_t v) {
    uint32_t r;
    asm("max.f16x2 %0, %1, %2;" : "=r"(r) : "r"(v), "r"(0u));
    return r;
}
__device__ __forceinline__ uint32_t shfl_u(uint32_t v, int src) {
    return __shfl_sync(0xffffffffu, v, src);
}

// ---- fused dual-tile hidden layer, fp16 acc: ONE ldm4 feeds BOTH tiles' MMAs.
// np-major streaming keeps D live-set small (16 words).
template<int KT, int STRIDE, int RBASE>
__device__ __forceinline__ void layer_h2(uint32_t abase,
                                         const uint32_t ainA[2][4][4],
                                         const uint32_t ainB[2][4][4],
                                         uint32_t aoutA[2][4][4],
                                         uint32_t aoutB[2][4][4])
{
    uint32_t bh[2][4];
    ldm4(bh[0], abase + (uint32_t)RBASE);

    #pragma unroll
    for (int np = 0; np < 4; np++) {
        uint32_t DA[2][2][2], DB[2][2][2];
        #pragma unroll
        for (int b = 0; b < 2; b++)
            #pragma unroll
            for (int nt = 0; nt < 2; nt++) {
                DA[b][nt][0] = 0u; DA[b][nt][1] = 0u;
                DB[b][nt][0] = 0u; DB[b][nt][1] = 0u;
            }
        #pragma unroll
        for (int kt = 0; kt < KT; kt++) {
            const int idx = np * KT + kt;
            if (idx + 1 < 4 * KT) {
                const int np1 = (idx + 1) / KT, kt1 = (idx + 1) % KT;
                ldm4(bh[(idx + 1) & 1],
                     abase + (uint32_t)(RBASE + np1 * 16 * STRIDE + kt1 * 32));
            }
            const uint32_t* cur = bh[idx & 1];
            #pragma unroll
            for (int b = 0; b < 2; b++) {
                mma16816h(DA[b][0], ainA[b][kt], cur[0], cur[1]);
                mma16816h(DA[b][1], ainA[b][kt], cur[2], cur[3]);
                mma16816h(DB[b][0], ainB[b][kt], cur[0], cur[1]);
                mma16816h(DB[b][1], ainB[b][kt], cur[2], cur[3]);
            }
        }
        #pragma unroll
        for (int b = 0; b < 2; b++) {
            aoutA[b][np][0] = relu2(DA[b][0][0]);
            aoutA[b][np][1] = relu2(DA[b][0][1]);
            aoutA[b][np][2] = relu2(DA[b][1][0]);
            aoutA[b][np][3] = relu2(DA[b][1][1]);
            aoutB[b][np][0] = relu2(DB[b][0][0]);
            aoutB[b][np][1] = relu2(DB[b][0][1]);
            aoutB[b][np][2] = relu2(DB[b][1][0]);
            aoutB[b][np][3] = relu2(DB[b][1][1]);
        }
    }
}

// store W[K][N] (row-major) transposed into padded rows, fp16
__device__ __forceinline__ void fill_w(const float* __restrict__ W, int K, int N,
                                       int rbase, int stride, char* smem, int tid)
{
    char* wdst = smem + rbase;
    for (int idx = tid; idx < K * N; idx += TPB) {
        int k = idx / N, nn = idx % N;
        __half hb = __float2half(W[idx]);
        *reinterpret_cast<uint16_t*>(wdst + nn * stride + 2 * k) =
            *reinterpret_cast<uint16_t*>(&hb);
    }
}
// wc0 with permuted K rows: src 0..2 (views) -> k 16..18; src 3..17 (g1..g15) -> k 1..15.
__device__ __forceinline__ void fill_wc0(const float* __restrict__ W, char* smem, int tid)
{
    char* wdst = smem + RB_C0;
    for (int idx = tid; idx < 18 * 64; idx += TPB) {
        int k = idx / 64, nn = idx % 64;
        int kd = (k < 3) ? (16 + k) : (k - 2);
        __half hb = __float2half(W[idx]);
        *reinterpret_cast<uint16_t*>(wdst + nn * ST_C0 + 2 * kd) =
            *reinterpret_cast<uint16_t*>(&hb);
    }
}

__global__ void __launch_bounds__(TPB, 2) nerf_hmma_kernel(
    const float* __restrict__ x,
    const float* __restrict__ ws0, const float* __restrict__ ws1,
    const float* __restrict__ ws2, const float* __restrict__ wc0,
    const float* __restrict__ wc1, const float* __restrict__ wc2,
    const float* __restrict__ wc3,
    float* __restrict__ out, int n)
{
    extern __shared__ char sm[];
    const uint32_t smb = smem_u32(sm);
    const int tid  = threadIdx.x;
    const int wid  = tid >> 5;
    const int lane = tid & 31;
    const int g4   = lane >> 2;
    const int m4   = lane & 3;

    for (int t = tid; t < WT_BYTES / 4; t += TPB)
        reinterpret_cast<uint32_t*>(sm)[t] = 0u;
    __syncthreads();
    fill_w(ws0,  3, 64, RB_S0, ST_S0, sm, tid);
    fill_w(ws1, 64, 64, RB_S1, ST_64, sm, tid);
    fill_w(ws2, 64, 16, RB_S2, ST_64, sm, tid);
    fill_wc0(wc0, sm, tid);
    fill_w(wc1, 64, 64, RB_C1, ST_64, sm, tid);
    fill_w(wc2, 64, 64, RB_C2, ST_64, sm, tid);
    fill_w(wc3, 64,  3, RB_C3, ST_64, sm, tid);
    __syncthreads();

    // per-lane ldmatrix base addresses (one per stride class)
    const int mm = lane >> 3, rr = lane & 7;
    const int qrow = ((mm >= 2) ? 8 : 0) + rr;
    const uint32_t tsel = (mm & 1) ? 16u : 0u;
    const uint32_t a48  = smb + (uint32_t)(qrow * ST_S0) + tsel;
    const uint32_t a80  = smb + (uint32_t)(qrow * ST_C0) + tsel;
    const uint32_t a144 = smb + (uint32_t)(qrow * ST_64) + tsel;
    const uint32_t a2   = smb + (uint32_t)(rr   * ST_64) + tsel;   // ldm2 (C3)

    // per-warp output staging: two 32x5 float regions (tile A, tile B)
    float* outbA = reinterpret_cast<float*>(sm + SM_OUT) + wid * (2 * 32 * 5);
    float* outbB = outbA + 32 * 5;

    const int ntiles = n / TILE;
    const int half   = ntiles >> 1;

    // ---- prefetch first pair's x ----
    float2 pA0, pA1, pA2, pB0, pB1, pB2;
    int tile = blockIdx.x;
    if (tile < half) {
        const float* xa = x + (size_t)(tile * TILE + wid * 32 + lane) * 6;
        pA0 = *reinterpret_cast<const float2*>(xa);
        pA1 = *reinterpret_cast<const float2*>(xa + 2);
        pA2 = *reinterpret_cast<const float2*>(xa + 4);
        const float* xb = x + (size_t)((tile + half) * TILE + wid * 32 + lane) * 6;
        pB0 = *reinterpret_cast<const float2*>(xb);
        pB1 = *reinterpret_cast<const float2*>(xb + 2);
        pB2 = *reinterpret_cast<const float2*>(xb + 4);
    }

    #pragma unroll 1
    for (; tile < half; tile += gridDim.x) {
        const int rowA = tile * TILE + wid * 32;
        const int rowB = (tile + half) * TILE + wid * 32;

        const uint32_t wA0 = pack2(pA0.x, pA0.y), wA1 = pack2(pA1.x, 0.0f);
        const uint32_t wA8 = pack2(pA1.y, pA2.x), wA9 = pack2(pA2.y, 0.0f);
        const uint32_t wB0 = pack2(pB0.x, pB0.y), wB1 = pack2(pB1.x, 0.0f);
        const uint32_t wB8 = pack2(pB1.y, pB2.x), wB9 = pack2(pB2.y, 0.0f);

        const int tnext = tile + gridDim.x;
        if (tnext < half) {
            const float* xa = x + (size_t)(tnext * TILE + wid * 32 + lane) * 6;
            pA0 = *reinterpret_cast<const float2*>(xa);
            pA1 = *reinterpret_cast<const float2*>(xa + 2);
            pA2 = *reinterpret_cast<const float2*>(xa + 4);
            const float* xb = x + (size_t)((tnext + half) * TILE + wid * 32 + lane) * 6;
            pB0 = *reinterpret_cast<const float2*>(xb);
            pB1 = *reinterpret_cast<const float2*>(xb + 2);
            pB2 = *reinterpret_cast<const float2*>(xb + 4);
        }

        uint32_t A0a[2][4][4], A1a[2][4][4], A0b[2][4][4], A1b[2][4][4];

        // ---- build S0 A frags via shfl (both tiles) ----
        #pragma unroll
        for (int b = 0; b < 2; b++) {
            int r0 = b*16 + g4, r1 = r0 + 8;
            uint32_t uA00 = shfl_u(wA0, r0), uA01 = shfl_u(wA1, r0);
            uint32_t uA10 = shfl_u(wA0, r1), uA11 = shfl_u(wA1, r1);
            A0a[b][0][0] = (m4 == 0) ? uA00 : (m4 == 1) ? uA01 : 0u;
            A0a[b][0][1] = (m4 == 0) ? uA10 : (m4 == 1) ? uA11 : 0u;
            A0a[b][0][2] = 0u; A0a[b][0][3] = 0u;
            uint32_t uB00 = shfl_u(wB0, r0), uB01 = shfl_u(wB1, r0);
            uint32_t uB10 = shfl_u(wB0, r1), uB11 = shfl_u(wB1, r1);
            A0b[b][0][0] = (m4 == 0) ? uB00 : (m4 == 1) ? uB01 : 0u;
            A0b[b][0][1] = (m4 == 0) ? uB10 : (m4 == 1) ? uB11 : 0u;
            A0b[b][0][2] = 0u; A0b[b][0][3] = 0u;
        }

        // ---- S0: 16 -> 64; S1: 64 -> 64 (dual-tile fused) ----
        layer_h2<1, ST_S0, RB_S0>(a48,  A0a, A0b, A1a, A1b);
        layer_h2<4, ST_64, RB_S1>(a144, A1a, A1b, A0a, A0b);

        // ---- S2: 64 -> 16 (fp32 acc, no relu), dual-tile fused ----
        float CsA[2][2][4], CsB[2][2][4];
        {
            #pragma unroll
            for (int b = 0; b < 2; b++)
                #pragma unroll
                for (int j = 0; j < 2; j++)
                    #pragma unroll
                    for (int i = 0; i < 4; i++) { CsA[b][j][i] = 0.0f; CsB[b][j][i] = 0.0f; }
            uint32_t bh[2][4];
            ldm4(bh[0], a144 + (uint32_t)RB_S2);
            #pragma unroll
            for (int kt = 0; kt < 4; kt++) {
                if (kt + 1 < 4)
                    ldm4(bh[(kt + 1) & 1], a144 + (uint32_t)(RB_S2 + (kt + 1) * 32));
                const uint32_t* cur = bh[kt & 1];
                #pragma unroll
                for (int b = 0; b < 2; b++) {
                    mma16816(CsA[b][0], A0a[b][kt], cur[0], cur[1]);
                    mma16816(CsA[b][1], A0a[b][kt], cur[2], cur[3]);
                    mma16816(CsB[b][0], A0b[b][kt], cur[0], cur[1]);
                    mma16816(CsB[b][1], A0b[b][kt], cur[2], cur[3]);
                }
            }
        }

        // sigma (lane m4==0 holds col 0 for rows r0/r1), both tiles
        #pragma unroll
        for (int b = 0; b < 2; b++) {
            if (m4 == 0) {
                int r0 = b*16 + g4, r1 = r0 + 8;
                float a0 = CsA[b][0][0], a2v = CsA[b][0][2];
                outbA[r0*5 + 3] = fmaxf(a0, 0.f) + log1pf(expf(-fabsf(a0)));
                outbA[r1*5 + 3] = fmaxf(a2v, 0.f) + log1pf(expf(-fabsf(a2v)));
                float b0v = CsB[b][0][0], b2v = CsB[b][0][2];
                outbB[r0*5 + 3] = fmaxf(b0v, 0.f) + log1pf(expf(-fabsf(b0v)));
                outbB[r1*5 + 3] = fmaxf(b2v, 0.f) + log1pf(expf(-fabsf(b2v)));
            }
        }

        // ---- build C0 A frags: kt=0 in-lane repack of S2 C-frags; kt=1 views via shfl ----
        #pragma unroll
        for (int b = 0; b < 2; b++) {
            int r0 = b*16 + g4, r1 = r0 + 8;
            A0a[b][0][0] = pack2(CsA[b][0][0], CsA[b][0][1]);
            A0a[b][0][1] = pack2(CsA[b][0][2], CsA[b][0][3]);
            A0a[b][0][2] = pack2(CsA[b][1][0], CsA[b][1][1]);
            A0a[b][0][3] = pack2(CsA[b][1][2], CsA[b][1][3]);
            uint32_t vA00 = shfl_u(wA8, r0), vA01 = shfl_u(wA9, r0);
            uint32_t vA10 = shfl_u(wA8, r1), vA11 = shfl_u(wA9, r1);
            A0a[b][1][0] = (m4 == 0) ? vA00 : (m4 == 1) ? vA01 : 0u;
            A0a[b][1][1] = (m4 == 0) ? vA10 : (m4 == 1) ? vA11 : 0u;
            A0a[b][1][2] = 0u; A0a[b][1][3] = 0u;

            A0b[b][0][0] = pack2(CsB[b][0][0], CsB[b][0][1]);
            A0b[b][0][1] = pack2(CsB[b][0][2], CsB[b][0][3]);
            A0b[b][0][2] = pack2(CsB[b][1][0], CsB[b][1][1]);
            A0b[b][0][3] = pack2(CsB[b][1][2], CsB[b][1][3]);
            uint32_t vB00 = shfl_u(wB8, r0), vB01 = shfl_u(wB9, r0);
            uint32_t vB10 = shfl_u(wB8, r1), vB11 = shfl_u(wB9, r1);
            A0b[b][1][0] = (m4 == 0) ? vB00 : (m4 == 1) ? vB01 : 0u;
            A0b[b][1][1] = (m4 == 0) ? vB10 : (m4 == 1) ? vB11 : 0u;
            A0b[b][1][2] = 0u; A0b[b][1][3] = 0u;
        }

        // ---- C0: 32 -> 64; C1, C2: 64 -> 64 (dual-tile fused) ----
        layer_h2<2, ST_C0, RB_C0>(a80,  A0a, A0b, A1a, A1b);
        layer_h2<4, ST_64, RB_C1>(a144, A1a, A1b, A0a, A0b);
        layer_h2<4, ST_64, RB_C2>(a144, A0a, A0b, A1a, A1b);

        // ---- C3: 64 -> 3 (fp32 acc, N padded to 8), dual-tile fused ----
        {
            float CcA[2][4], CcB[2][4];
            #pragma unroll
            for (int b = 0; b < 2; b++)
                #pragma unroll
                for (int i = 0; i < 4; i++) { CcA[b][i] = 0.0f; CcB[b][i] = 0.0f; }
            uint32_t bh[2][2];
            ldm2(bh[0], a2 + (uint32_t)RB_C3);
            #pragma unroll
            for (int kt = 0; kt < 4; kt++) {
                if (kt + 1 < 4)
                    ldm2(bh[(kt + 1) & 1], a2 + (uint32_t)(RB_C3 + (kt + 1) * 32));
                const uint32_t* cur = bh[kt & 1];
                #pragma unroll
                for (int b = 0; b < 2; b++) {
                    mma16816(CcA[b], A1a[b][kt], cur[0], cur[1]);
                    mma16816(CcB[b], A1b[b][kt], cur[0], cur[1]);
                }
            }
            #pragma unroll
            for (int b = 0; b < 2; b++) {
                int r0 = b*16 + g4, r1 = r0 + 8;
                if (m4 == 0) {
                    outbA[r0*5+0] = CcA[b][0]; outbA[r0*5+1] = CcA[b][1];
                    outbA[r1*5+0] = CcA[b][2]; outbA[r1*5+1] = CcA[b][3];
                    outbB[r0*5+0] = CcB[b][0]; outbB[r0*5+1] = CcB[b][1];
                    outbB[r1*5+0] = CcB[b][2]; outbB[r1*5+1] = CcB[b][3];
                } else if (m4 == 1) {
                    outbA[r0*5+2] = CcA[b][0];
                    outbA[r1*5+2] = CcA[b][2];
                    outbB[r0*5+2] = CcB[b][0];
                    outbB[r1*5+2] = CcB[b][2];
                }
            }
        }
        __syncwarp();

        // ---- final stores: lane l writes row l of each tile ----
        {
            float4 rA;
            rA.x = outbA[lane*5+0]; rA.y = outbA[lane*5+1];
            rA.z = outbA[lane*5+2]; rA.w = outbA[lane*5+3];
            reinterpret_cast<float4*>(out)[rowA + lane] = rA;
            float4 rB;
            rB.x = outbB[lane*5+0]; rB.y = outbB[lane*5+1];
            rB.z = outbB[lane*5+2]; rB.w = outbB[lane*5+3];
            reinterpret_cast<float4*>(out)[rowB + lane] = rB;
        }
        __syncwarp();
    }
}

extern "C" void kernel_launch(void* const* d_in, const int* in_sizes, int n_in,
                              void* d_out, int out_size) {
    const float* x   = (const float*)d_in[0];
    const float* ws0 = (const float*)d_in[1];
    const float* ws1 = (const float*)d_in[2];
    const float* ws2 = (const float*)d_in[3];
    const float* wc0 = (const float*)d_in[4];
    const float* wc1 = (const float*)d_in[5];
    const float* wc2 = (const float*)d_in[6];
    const float* wc3 = (const float*)d_in[7];
    float* out = (float*)d_out;

    int n = in_sizes[0] / 6;
    int ntiles = n / TILE;
    int half = ntiles >> 1;

    cudaFuncSetAttribute(nerf_hmma_kernel,
                         cudaFuncAttributeMaxDynamicSharedMemorySize, SMEM_TOTAL);
    int grid = 296;                      // 2 persistent CTAs per SM
    if (grid > half) grid = half;
    nerf_hmma_kernel<<<grid, TPB, SMEM_TOTAL>>>(x, ws0, ws1, ws2, wc0, wc1, wc2, wc3, out, n);
}